// round 15
// baseline (speedup 1.0000x reference)
#include <cuda_runtime.h>
#include <cuda_fp16.h>
#include <cstdint>
#include <cstddef>

// Problem constants
#define BATCH_N 4
#define T_SEQ   2048
#define NH      16
#define HD      64
#define DMODEL  1024
#define M_ROWS  (BATCH_N * T_SEQ)   // 8192

// GEMM tiling (best config)
#define BM 128
#define BN 128
#define BK 64
#define STAGES 3
#define NKT (DMODEL / BK)        // 16
#define LDH 72
#define STAGE_HALVES (2 * 128 * LDH)
#define GEMM_SMEM (STAGES * STAGE_HALVES * 2)   // 110592 bytes
#define LDO 136

// Flash-attention smem: tiles [64][72] halves = 9216 B
#define FA_QS    0
#define FA_KS0   9216
#define FA_KS1   18432
#define FA_VS0   27648
#define FA_VS1   36864
#define FA_SMEM  46080

// Scratch (all fp16 activations)
__device__ __half g_xh [(size_t)M_ROWS * DMODEL];
__device__ __half g_wh [4 * (size_t)DMODEL * DMODEL];
__device__ __half g_Qh [(size_t)BATCH_N * NH * T_SEQ * HD];
__device__ __half g_Kh [(size_t)BATCH_N * NH * T_SEQ * HD];
__device__ __half g_Vt [(size_t)BATCH_N * NH * HD * T_SEQ];  // [B,H,hd,T]
__device__ __half g_ctxh[(size_t)M_ROWS * DMODEL];

// ---------------------------------------------------------------------------
// Helpers
// ---------------------------------------------------------------------------
__device__ __forceinline__ uint32_t smem_u32(const void* p) {
    uint32_t a;
    asm("{ .reg .u64 t; cvta.to.shared.u64 t, %1; cvt.u32.u64 %0, t; }"
        : "=r"(a) : "l"(p));
    return a;
}
__device__ __forceinline__ float ex2(float x) {
    float y;
    asm("ex2.approx.f32 %0, %1;" : "=f"(y) : "f"(x));
    return y;
}
__device__ __forceinline__ void cpa16(uint32_t s, const void* g) {
    asm volatile("cp.async.cg.shared.global [%0], [%1], 16;" :: "r"(s), "l"(g));
}
__device__ __forceinline__ void cpa_commit() {
    asm volatile("cp.async.commit_group;");
}
__device__ __forceinline__ void mma_f16(float* d, const uint32_t* a,
                                        const uint32_t* b) {
    asm volatile(
        "mma.sync.aligned.m16n8k16.row.col.f32.f16.f16.f32 "
        "{%0,%1,%2,%3}, {%4,%5,%6,%7}, {%8,%9}, {%0,%1,%2,%3};"
        : "+f"(d[0]), "+f"(d[1]), "+f"(d[2]), "+f"(d[3])
        : "r"(a[0]), "r"(a[1]), "r"(a[2]), "r"(a[3]), "r"(b[0]), "r"(b[1]));
}
// fp16-accumulator MMA (S only: 4-deep chain)
__device__ __forceinline__ void mma_f16acc(uint32_t* d, const uint32_t* a,
                                           const uint32_t* b) {
    asm volatile(
        "mma.sync.aligned.m16n8k16.row.col.f16.f16.f16.f16 "
        "{%0,%1}, {%2,%3,%4,%5}, {%6,%7}, {%0,%1};"
        : "+r"(d[0]), "+r"(d[1])
        : "r"(a[0]), "r"(a[1]), "r"(a[2]), "r"(a[3]), "r"(b[0]), "r"(b[1]));
}
__device__ __forceinline__ void ldsm4(uint32_t& r0, uint32_t& r1,
                                      uint32_t& r2, uint32_t& r3, uint32_t a) {
    asm volatile("ldmatrix.sync.aligned.m8n8.x4.shared.b16 {%0,%1,%2,%3}, [%4];"
                 : "=r"(r0), "=r"(r1), "=r"(r2), "=r"(r3) : "r"(a));
}

// ---------------------------------------------------------------------------
// f32 -> fp16 RN conversion: x + all 4 weights in ONE launch
// ---------------------------------------------------------------------------
#define XN4 ((M_ROWS * DMODEL) / 4)
#define WN4 ((DMODEL * DMODEL) / 4)

__global__ void __launch_bounds__(256)
cvt_all(const float4* __restrict__ x,
        const float4* __restrict__ w0, const float4* __restrict__ w1,
        const float4* __restrict__ w2, const float4* __restrict__ w3,
        uint2* __restrict__ xh, uint2* __restrict__ wh)
{
    int i = blockIdx.x * 256 + threadIdx.x;
    const float4* s;
    uint2* d;
    int o;
    if (i < XN4) { s = x; d = xh; o = i; }
    else {
        int j = i - XN4;
        int w = j / WN4;
        o = j - w * WN4;
        s = (w == 0) ? w0 : (w == 1) ? w1 : (w == 2) ? w2 : w3;
        d = wh + (size_t)w * WN4;
    }
    float4 v = s[o];
    __half2 h0 = __floats2half2_rn(v.x, v.y);
    __half2 h1 = __floats2half2_rn(v.z, v.w);
    d[o] = make_uint2(*(uint32_t*)&h0, *(uint32_t*)&h1);
}

// ---------------------------------------------------------------------------
// fp16 tensor-core GEMM (f32 acc, single-barrier multistage pipeline)
// ---------------------------------------------------------------------------
__device__ __forceinline__ void load_stage(const __half* __restrict__ A,
                                           const __half* __restrict__ W,
                                           int m0, int n0, int kt,
                                           uint32_t sA, uint32_t sB, int tid)
{
#pragma unroll
    for (int p = 0; p < 4; p++) {
        int i = tid + p * 256;
        int r = i >> 3, c = i & 7;
        cpa16(sA + (uint32_t)(r * (LDH * 2) + c * 16),
              A + (size_t)(m0 + r) * DMODEL + kt * BK + c * 8);
    }
#pragma unroll
    for (int p = 0; p < 4; p++) {
        int i = tid + p * 256;
        int r = i >> 3, c = i & 7;
        cpa16(sB + (uint32_t)(r * (LDH * 2) + c * 16),
              W + (size_t)(n0 + r) * DMODEL + kt * BK + c * 8);
    }
}

template <bool SPLIT, bool BIAS>
__global__ void __launch_bounds__(256, 2)
gemm_fp16(const __half* __restrict__ A,
          const __half* __restrict__ W0, const __half* __restrict__ W1,
          const __half* __restrict__ W2,
          void* __restrict__ C0, void* __restrict__ C1, void* __restrict__ C2,
          const float* __restrict__ bias)
{
    extern __shared__ __align__(16) __half smem[];
    const uint32_t sbase = smem_u32(smem);

    const int tid  = threadIdx.x;
    const int wid  = tid >> 5;
    const int lane = tid & 31;
    const int warp_m = wid & 1;
    const int warp_n = wid >> 1;
    const int lr = lane >> 2;
    const int lc = lane & 3;

    const int m0 = blockIdx.y * BM;
    const int n0 = blockIdx.x * BN;
    const int z = blockIdx.z;
    const __half* W = (z == 0) ? W0 : (z == 1) ? W1 : W2;
    void* C = (z == 0) ? C0 : (z == 1) ? C1 : C2;

    const uint32_t a_off = (uint32_t)(((warp_m * 64 + (lane & 15)) * LDH
                                       + (lane >> 4) * 8) * 2);
    const uint32_t b_off = (uint32_t)(((warp_n * 32 + (lane & 7)
                                        + ((lane >> 4) & 1) * 8) * LDH
                                       + ((lane >> 3) & 1) * 8) * 2);

    float acc[4][4][4];
#pragma unroll
    for (int mi = 0; mi < 4; mi++)
#pragma unroll
        for (int ni = 0; ni < 4; ni++)
#pragma unroll
            for (int k = 0; k < 4; k++) acc[mi][ni][k] = 0.0f;

#pragma unroll
    for (int s = 0; s < STAGES - 1; s++) {
        uint32_t sA = sbase + (uint32_t)(s * STAGE_HALVES) * 2;
        load_stage(A, W, m0, n0, s, sA, sA + 128 * LDH * 2, tid);
        cpa_commit();
    }

    for (int kt = 0; kt < NKT; kt++) {
        asm volatile("cp.async.wait_group %0;" :: "n"(STAGES - 2));
        __syncthreads();

        const int wt = kt + STAGES - 1;
        if (wt < NKT) {
            const int ws = wt % STAGES;
            uint32_t sA = sbase + (uint32_t)(ws * STAGE_HALVES) * 2;
            load_stage(A, W, m0, n0, wt, sA, sA + 128 * LDH * 2, tid);
        }
        cpa_commit();

        const int s = kt % STAGES;
        const uint32_t As_u = sbase + (uint32_t)(s * STAGE_HALVES) * 2;
        const uint32_t Bs_u = As_u + 128 * LDH * 2;

#pragma unroll
        for (int ks = 0; ks < 4; ks++) {
            uint32_t a[4][4], b[4][2];
#pragma unroll
            for (int mi = 0; mi < 4; mi++)
                ldsm4(a[mi][0], a[mi][1], a[mi][2], a[mi][3],
                      As_u + a_off + (uint32_t)((mi * 16 * LDH + ks * 16) * 2));
#pragma unroll
            for (int bp = 0; bp < 2; bp++)
                ldsm4(b[2 * bp][0], b[2 * bp][1], b[2 * bp + 1][0],
                      b[2 * bp + 1][1],
                      Bs_u + b_off + (uint32_t)((bp * 16 * LDH + ks * 16) * 2));
#pragma unroll
            for (int mi = 0; mi < 4; mi++)
#pragma unroll
                for (int ni = 0; ni < 4; ni++)
                    mma_f16(acc[mi][ni], a[mi], b[ni]);
        }
    }

    if (SPLIT) {
        __syncthreads();
        const int bb = m0 >> 11;
        const int t0 = m0 & (T_SEQ - 1);
        const int h0 = n0 >> 6;

        if (z < 2) {
#pragma unroll
            for (int mi = 0; mi < 4; mi++)
#pragma unroll
                for (int ni = 0; ni < 4; ni++)
#pragma unroll
                    for (int half_i = 0; half_i < 2; half_i++) {
                        const int ml = warp_m * 64 + mi * 16 + lr + half_i * 8;
                        const int nl = warp_n * 32 + ni * 8 + lc * 2;
                        *(__half2*)&smem[ml * LDO + nl] =
                            __floats2half2_rn(acc[mi][ni][half_i * 2],
                                              acc[mi][ni][half_i * 2 + 1]);
                    }
            __syncthreads();
            __half* Ch = (__half*)C;
#pragma unroll
            for (int p = 0; p < 8; p++) {
                int i = tid + p * 256;
                int c  = i & 7;
                int h2 = (i >> 3) & 1;
                int t  = i >> 4;
                uint4 val = *(uint4*)&smem[t * LDO + h2 * 64 + c * 8];
                __half* dst = Ch + (((size_t)(bb * NH + h0 + h2) * T_SEQ
                                     + t0 + t) * HD + c * 8);
                *(uint4*)dst = val;
            }
        } else {
#pragma unroll
            for (int mi = 0; mi < 4; mi++)
#pragma unroll
                for (int ni = 0; ni < 4; ni++)
#pragma unroll
                    for (int half_i = 0; half_i < 2; half_i++) {
                        const int ml = warp_m * 64 + mi * 16 + lr + half_i * 8;
                        const int nl = warp_n * 32 + ni * 8 + lc * 2;
                        smem[nl * LDO + ml] =
                            __float2half_rn(acc[mi][ni][half_i * 2]);
                        smem[(nl + 1) * LDO + ml] =
                            __float2half_rn(acc[mi][ni][half_i * 2 + 1]);
                    }
            __syncthreads();
            __half* Vt = (__half*)C;
#pragma unroll
            for (int p = 0; p < 8; p++) {
                int i = tid + p * 256;
                int c  = i & 15;
                int dn = i >> 4;
                int h2 = dn >> 6;
                int d  = dn & 63;
                uint4 val = *(uint4*)&smem[dn * LDO + c * 8];
                __half* dst = Vt + (((size_t)(bb * NH + h0 + h2) * HD + d)
                                    * T_SEQ + t0 + c * 8);
                *(uint4*)dst = val;
            }
        }
    } else {
#pragma unroll
        for (int mi = 0; mi < 4; mi++) {
#pragma unroll
            for (int ni = 0; ni < 4; ni++) {
                const int n = n0 + warp_n * 32 + ni * 8 + lc * 2;
#pragma unroll
                for (int half_i = 0; half_i < 2; half_i++) {
                    const int mg = m0 + warp_m * 64 + mi * 16 + lr + half_i * 8;
                    float v0 = acc[mi][ni][half_i * 2 + 0];
                    float v1 = acc[mi][ni][half_i * 2 + 1];
                    if (BIAS) { v0 += bias[n]; v1 += bias[n + 1]; }
                    float* dst = (float*)C + (size_t)mg * DMODEL + n;
                    *(float2*)dst = make_float2(v0, v1);
                }
            }
        }
    }
}

// ---------------------------------------------------------------------------
// Tensor-core flash attention (causal), fp16; S fp16-acc; Q frags HOISTED
// ---------------------------------------------------------------------------
__device__ __forceinline__ void fa_load_kv(const __half* __restrict__ Kh,
                                           const __half* __restrict__ Vtg,
                                           uint32_t ks, uint32_t vs,
                                           size_t hb, size_t vb, int j0, int tid)
{
#pragma unroll
    for (int p = 0; p < 4; p++) {
        int i = p * 128 + tid;
        int r = i >> 3, c = i & 7;
        cpa16(ks + (uint32_t)(r * 144 + c * 16),
              Kh + hb + (size_t)(j0 + r) * HD + c * 8);
    }
#pragma unroll
    for (int p = 0; p < 4; p++) {
        int i = p * 128 + tid;
        int d = i >> 3, c = i & 7;
        cpa16(vs + (uint32_t)(d * 144 + c * 16),
              Vtg + vb + (size_t)d * T_SEQ + j0 + c * 8);
    }
}

__global__ void __launch_bounds__(128, 4)
flash_attn_tc(const __half* __restrict__ Qh, const __half* __restrict__ Kh,
              const __half* __restrict__ Vtg, __half* __restrict__ ctx)
{
    extern __shared__ __align__(16) char sm[];

    const int qt = (T_SEQ / 64 - 1) - blockIdx.x;   // heavy first
    const int h  = blockIdx.y;
    const int b  = blockIdx.z;
    const int i0 = qt * 64;
    const size_t hb = ((size_t)(b * NH + h)) * T_SEQ * HD;
    const size_t vb = ((size_t)(b * NH + h)) * HD * T_SEQ;

    const int tid  = threadIdx.x;
    const int wid  = tid >> 5;
    const int lane = tid & 31;
    const int lr = lane >> 2;
    const int lc = lane & 3;

    const uint32_t Qs_u  = smem_u32(sm) + FA_QS;
    const uint32_t Ks_u0 = smem_u32(sm) + FA_KS0;
    const uint32_t Vs_u0 = smem_u32(sm) + FA_VS0;

    const uint32_t qa_off = (uint32_t)(((wid * 16 + (lane & 15)) * 72
                                        + (lane >> 4) * 8) * 2);
    const uint32_t kb_off = (uint32_t)((((lane & 7) + ((lane >> 4) & 1) * 8) * 72
                                        + ((lane >> 3) & 1) * 8) * 2);

    {
#pragma unroll
        for (int p = 0; p < 4; p++) {
            int i = p * 128 + tid;
            int r = i >> 3, c = i & 7;
            cpa16(Qs_u + (uint32_t)(r * 144 + c * 16),
                  Qh + hb + (size_t)(i0 + r) * HD + c * 8);
        }
        fa_load_kv(Kh, Vtg, Ks_u0, Vs_u0, hb, vb, 0, tid);
        cpa_commit();
    }

    float m0 = -1e30f, m1 = -1e30f, l0 = 0.0f, l1 = 0.0f;
    float o[8][4];
#pragma unroll
    for (int nf = 0; nf < 8; nf++)
#pragma unroll
        for (int j = 0; j < 4; j++) o[nf][j] = 0.0f;

    uint32_t qa[4][4];          // hoisted Q fragments (loop-invariant)

    const int qr = wid * 16 + lr;
    const float kk = 0.18033688011112042f;  // log2(e)/sqrt(64)

    for (int jt = 0; jt <= qt; jt++) {
        if (jt < qt) {
            const int nb = (jt + 1) & 1;
            fa_load_kv(Kh, Vtg, Ks_u0 + nb * 9216, Vs_u0 + nb * 9216,
                       hb, vb, (jt + 1) * 64, tid);
        }
        cpa_commit();
        asm volatile("cp.async.wait_group 1;");
        __syncthreads();

        if (jt == 0) {          // Q tile stable after first barrier: load ONCE
#pragma unroll
            for (int kc = 0; kc < 4; kc++)
                ldsm4(qa[kc][0], qa[kc][1], qa[kc][2], qa[kc][3],
                      Qs_u + qa_off + kc * 32);
        }

        const uint32_t Ks_u = Ks_u0 + (jt & 1) * 9216;
        const uint32_t Vs_u = Vs_u0 + (jt & 1) * 9216;

        // ---- S = Q @ K^T (fp16 acc) ----
        uint32_t sh[8][2];
#pragma unroll
        for (int nf = 0; nf < 8; nf++) { sh[nf][0] = 0u; sh[nf][1] = 0u; }

#pragma unroll
        for (int kc = 0; kc < 4; kc++) {
#pragma unroll
            for (int np = 0; np < 4; np++) {
                uint32_t b0, b1, b2, b3;
                ldsm4(b0, b1, b2, b3,
                      Ks_u + kb_off + (uint32_t)((np * 16 * 72 + kc * 16) * 2));
                uint32_t bl[2] = { b0, b1 };
                uint32_t bh[2] = { b2, b3 };
                mma_f16acc(sh[2 * np],     qa[kc], bl);
                mma_f16acc(sh[2 * np + 1], qa[kc], bh);
            }
        }

        float s[8][4];
#pragma unroll
        for (int nf = 0; nf < 8; nf++) {
            float2 lo = __half22float2(*(__half2*)&sh[nf][0]);
            float2 hi = __half22float2(*(__half2*)&sh[nf][1]);
            s[nf][0] = lo.x; s[nf][1] = lo.y;
            s[nf][2] = hi.x; s[nf][3] = hi.y;
        }

        // ---- online softmax (exp2 domain) ----
        const bool diag = (jt == qt);
        float mx0 = -1e30f, mx1 = -1e30f;
#pragma unroll
        for (int nf = 0; nf < 8; nf++) {
            float e0 = s[nf][0] * kk, e1 = s[nf][1] * kk;
            float e2 = s[nf][2] * kk, e3 = s[nf][3] * kk;
            if (diag) {
                const int c0 = nf * 8 + lc * 2, c1 = c0 + 1;
                if (c0 > qr)     e0 = -1e30f;
                if (c1 > qr)     e1 = -1e30f;
                if (c0 > qr + 8) e2 = -1e30f;
                if (c1 > qr + 8) e3 = -1e30f;
            }
            s[nf][0] = e0; s[nf][1] = e1; s[nf][2] = e2; s[nf][3] = e3;
            mx0 = fmaxf(mx0, fmaxf(e0, e1));
            mx1 = fmaxf(mx1, fmaxf(e2, e3));
        }
        mx0 = fmaxf(mx0, __shfl_xor_sync(0xffffffffu, mx0, 1));
        mx0 = fmaxf(mx0, __shfl_xor_sync(0xffffffffu, mx0, 2));
        mx1 = fmaxf(mx1, __shfl_xor_sync(0xffffffffu, mx1, 1));
        mx1 = fmaxf(mx1, __shfl_xor_sync(0xffffffffu, mx1, 2));

        const float mn0 = fmaxf(m0, mx0), mn1 = fmaxf(m1, mx1);
        const float al0 = ex2(m0 - mn0),  al1 = ex2(m1 - mn1);

        uint32_t ph[8][2];
        float sum0 = 0.0f, sum1 = 0.0f;
#pragma unroll
        for (int nf = 0; nf < 8; nf++) {
            float p0 = ex2(s[nf][0] - mn0), p1 = ex2(s[nf][1] - mn0);
            float p2 = ex2(s[nf][2] - mn1), p3 = ex2(s[nf][3] - mn1);
            sum0 += p0 + p1;
            sum1 += p2 + p3;
            __half2 hlo = __floats2half2_rn(p0, p1);
            __half2 hhi = __floats2half2_rn(p2, p3);
            ph[nf][0] = *(uint32_t*)&hlo;
            ph[nf][1] = *(uint32_t*)&hhi;
        }
        sum0 += __shfl_xor_sync(0xffffffffu, sum0, 1);
        sum0 += __shfl_xor_sync(0xffffffffu, sum0, 2);
        sum1 += __shfl_xor_sync(0xffffffffu, sum1, 1);
        sum1 += __shfl_xor_sync(0xffffffffu, sum1, 2);
        l0 = l0 * al0 + sum0;
        l1 = l1 * al1 + sum1;
        m0 = mn0; m1 = mn1;
#pragma unroll
        for (int nf = 0; nf < 8; nf++) {
            o[nf][0] *= al0; o[nf][1] *= al0;
            o[nf][2] *= al1; o[nf][3] *= al1;
        }

        // ---- O += P @ V (fp32 acc) ----
#pragma unroll
        for (int kc = 0; kc < 4; kc++) {
            uint32_t a[4] = { ph[2 * kc][0], ph[2 * kc][1],
                              ph[2 * kc + 1][0], ph[2 * kc + 1][1] };
#pragma unroll
            for (int np = 0; np < 4; np++) {
                uint32_t b0, b1, b2, b3;
                ldsm4(b0, b1, b2, b3,
                      Vs_u + kb_off + (uint32_t)((np * 16 * 72 + kc * 16) * 2));
                uint32_t bl[2] = { b0, b1 };
                uint32_t bh[2] = { b2, b3 };
                mma_f16(o[2 * np],     a, bl);
                mma_f16(o[2 * np + 1], a, bh);
            }
        }
        __syncthreads();
    }

    // ---- epilogue ----
    const float inv0 = 1.0f / l0, inv1 = 1.0f / l1;
    const int t_lo = i0 + qr;
#pragma unroll
    for (int nf = 0; nf < 8; nf++) {
        const int d = nf * 8 + lc * 2;
        __half* p0 = ctx + ((size_t)(b * T_SEQ + t_lo)) * DMODEL + h * HD + d;
        *(__half2*)p0 = __floats2half2_rn(o[nf][0] * inv0, o[nf][1] * inv0);
        __half* p1 = p0 + (size_t)8 * DMODEL;
        *(__half2*)p1 = __floats2half2_rn(o[nf][2] * inv1, o[nf][3] * inv1);
    }
}

// ---------------------------------------------------------------------------

extern "C" void kernel_launch(void* const* d_in, const int* in_sizes, int n_in,
                              void* d_out, int out_size)
{
    const float* x  = (const float*)d_in[0];
    const float* wq = (const float*)d_in[1];
    const float* wk = (const float*)d_in[2];
    const float* wv = (const float*)d_in[3];
    const float* wo = (const float*)d_in[4];
    const float* bo = (const float*)d_in[5];
    float* out = (float*)d_out;

    __half *pXh, *pWh, *pQh, *pKh, *pVt, *pCtx;
    cudaGetSymbolAddress((void**)&pXh, g_xh);
    cudaGetSymbolAddress((void**)&pWh, g_wh);
    cudaGetSymbolAddress((void**)&pQh, g_Qh);
    cudaGetSymbolAddress((void**)&pKh, g_Kh);
    cudaGetSymbolAddress((void**)&pVt, g_Vt);
    cudaGetSymbolAddress((void**)&pCtx, g_ctxh);

    __half* pWq = pWh;
    __half* pWk = pWh + (size_t)DMODEL * DMODEL;
    __half* pWv = pWh + 2 * (size_t)DMODEL * DMODEL;
    __half* pWo = pWh + 3 * (size_t)DMODEL * DMODEL;

    cudaFuncSetAttribute(gemm_fp16<true, false>,
                         cudaFuncAttributeMaxDynamicSharedMemorySize, GEMM_SMEM);
    cudaFuncSetAttribute(gemm_fp16<false, true>,
                         cudaFuncAttributeMaxDynamicSharedMemorySize, GEMM_SMEM);
    cudaFuncSetAttribute(flash_attn_tc,
                         cudaFuncAttributeMaxDynamicSharedMemorySize, FA_SMEM);

    // 1) single-launch f32->fp16 conversion (x + 4 weights)
    {
        int total = XN4 + 4 * WN4;
        cvt_all<<<total / 256, 256>>>(
            (const float4*)x, (const float4*)wq, (const float4*)wk,
            (const float4*)wv, (const float4*)wo, (uint2*)pXh, (uint2*)pWh);
    }

    // 2) fused QKV projections (fp16 MMA, f32 acc)
    {
        dim3 grid(DMODEL / BN, M_ROWS / BM, 3);
        gemm_fp16<true, false><<<grid, 256, GEMM_SMEM>>>(
            pXh, pWq, pWk, pWv, pQh, pKh, pVt, nullptr);
    }

    // 3) tensor-core flash attention (fp16; S fp16-acc; Q frags hoisted)
    {
        dim3 fgrid(T_SEQ / 64, NH, BATCH_N);
        flash_attn_tc<<<fgrid, 128, FA_SMEM>>>(pQh, pKh, pVt, pCtx);
    }

    // 4) output projection + bias (fp32 out)
    {
        dim3 grid(DMODEL / BN, M_ROWS / BM, 1);
        gemm_fp16<false, true><<<grid, 256, GEMM_SMEM>>>(
            pCtx, pWo, pWo, pWo, out, out, out, bo);
    }
}

// round 16
// speedup vs baseline: 1.0145x; 1.0145x over previous
#include <cuda_runtime.h>
#include <cuda_fp16.h>
#include <cstdint>
#include <cstddef>

// Problem constants
#define BATCH_N 4
#define T_SEQ   2048
#define NH      16
#define HD      64
#define DMODEL  1024
#define M_ROWS  (BATCH_N * T_SEQ)   // 8192

// GEMM tiling (best config)
#define BM 128
#define BN 128
#define BK 64
#define STAGES 3
#define NKT (DMODEL / BK)        // 16
#define LDH 72
#define STAGE_HALVES (2 * 128 * LDH)
#define GEMM_SMEM (STAGES * STAGE_HALVES * 2)   // 110592 bytes
#define LDO 136

// Flash-attention smem: tiles [64][72] halves = 9216 B
#define FA_QS    0
#define FA_KS0   9216
#define FA_KS1   18432
#define FA_VS0   27648
#define FA_VS1   36864
#define FA_SMEM  46080

// Scratch (all fp16 activations)
__device__ __half g_xh [(size_t)M_ROWS * DMODEL];
__device__ __half g_wh [4 * (size_t)DMODEL * DMODEL];
__device__ __half g_Qh [(size_t)BATCH_N * NH * T_SEQ * HD];
__device__ __half g_Kh [(size_t)BATCH_N * NH * T_SEQ * HD];
__device__ __half g_Vt [(size_t)BATCH_N * NH * HD * T_SEQ];  // [B,H,hd,T]
__device__ __half g_ctxh[(size_t)M_ROWS * DMODEL];

// ---------------------------------------------------------------------------
// Helpers
// ---------------------------------------------------------------------------
__device__ __forceinline__ uint32_t smem_u32(const void* p) {
    uint32_t a;
    asm("{ .reg .u64 t; cvta.to.shared.u64 t, %1; cvt.u32.u64 %0, t; }"
        : "=r"(a) : "l"(p));
    return a;
}
__device__ __forceinline__ float ex2(float x) {
    float y;
    asm("ex2.approx.f32 %0, %1;" : "=f"(y) : "f"(x));
    return y;
}
__device__ __forceinline__ void cpa16(uint32_t s, const void* g) {
    asm volatile("cp.async.cg.shared.global [%0], [%1], 16;" :: "r"(s), "l"(g));
}
__device__ __forceinline__ void cpa_commit() {
    asm volatile("cp.async.commit_group;");
}
__device__ __forceinline__ void mma_f16(float* d, const uint32_t* a,
                                        const uint32_t* b) {
    asm volatile(
        "mma.sync.aligned.m16n8k16.row.col.f32.f16.f16.f32 "
        "{%0,%1,%2,%3}, {%4,%5,%6,%7}, {%8,%9}, {%0,%1,%2,%3};"
        : "+f"(d[0]), "+f"(d[1]), "+f"(d[2]), "+f"(d[3])
        : "r"(a[0]), "r"(a[1]), "r"(a[2]), "r"(a[3]), "r"(b[0]), "r"(b[1]));
}
// fp16-accumulator MMA (S only: 4-deep chain)
__device__ __forceinline__ void mma_f16acc(uint32_t* d, const uint32_t* a,
                                           const uint32_t* b) {
    asm volatile(
        "mma.sync.aligned.m16n8k16.row.col.f16.f16.f16.f16 "
        "{%0,%1}, {%2,%3,%4,%5}, {%6,%7}, {%0,%1};"
        : "+r"(d[0]), "+r"(d[1])
        : "r"(a[0]), "r"(a[1]), "r"(a[2]), "r"(a[3]), "r"(b[0]), "r"(b[1]));
}
__device__ __forceinline__ void ldsm4(uint32_t& r0, uint32_t& r1,
                                      uint32_t& r2, uint32_t& r3, uint32_t a) {
    asm volatile("ldmatrix.sync.aligned.m8n8.x4.shared.b16 {%0,%1,%2,%3}, [%4];"
                 : "=r"(r0), "=r"(r1), "=r"(r2), "=r"(r3) : "r"(a));
}

// ---------------------------------------------------------------------------
// f32 -> fp16 RN conversion: x + all 4 weights in ONE launch
// ---------------------------------------------------------------------------
#define XN4 ((M_ROWS * DMODEL) / 4)
#define WN4 ((DMODEL * DMODEL) / 4)

__global__ void __launch_bounds__(256)
cvt_all(const float4* __restrict__ x,
        const float4* __restrict__ w0, const float4* __restrict__ w1,
        const float4* __restrict__ w2, const float4* __restrict__ w3,
        uint2* __restrict__ xh, uint2* __restrict__ wh)
{
    int i = blockIdx.x * 256 + threadIdx.x;
    const float4* s;
    uint2* d;
    int o;
    if (i < XN4) { s = x; d = xh; o = i; }
    else {
        int j = i - XN4;
        int w = j / WN4;
        o = j - w * WN4;
        s = (w == 0) ? w0 : (w == 1) ? w1 : (w == 2) ? w2 : w3;
        d = wh + (size_t)w * WN4;
    }
    float4 v = s[o];
    __half2 h0 = __floats2half2_rn(v.x, v.y);
    __half2 h1 = __floats2half2_rn(v.z, v.w);
    d[o] = make_uint2(*(uint32_t*)&h0, *(uint32_t*)&h1);
}

// ---------------------------------------------------------------------------
// fp16 tensor-core GEMM (f32 acc, single-barrier multistage pipeline)
// ---------------------------------------------------------------------------
__device__ __forceinline__ void load_stage(const __half* __restrict__ A,
                                           const __half* __restrict__ W,
                                           int m0, int n0, int kt,
                                           uint32_t sA, uint32_t sB, int tid)
{
#pragma unroll
    for (int p = 0; p < 4; p++) {
        int i = tid + p * 256;
        int r = i >> 3, c = i & 7;
        cpa16(sA + (uint32_t)(r * (LDH * 2) + c * 16),
              A + (size_t)(m0 + r) * DMODEL + kt * BK + c * 8);
    }
#pragma unroll
    for (int p = 0; p < 4; p++) {
        int i = tid + p * 256;
        int r = i >> 3, c = i & 7;
        cpa16(sB + (uint32_t)(r * (LDH * 2) + c * 16),
              W + (size_t)(n0 + r) * DMODEL + kt * BK + c * 8);
    }
}

template <bool SPLIT, bool BIAS>
__global__ void __launch_bounds__(256, 2)
gemm_fp16(const __half* __restrict__ A,
          const __half* __restrict__ W0, const __half* __restrict__ W1,
          const __half* __restrict__ W2,
          void* __restrict__ C0, void* __restrict__ C1, void* __restrict__ C2,
          const float* __restrict__ bias)
{
    extern __shared__ __align__(16) __half smem[];
    const uint32_t sbase = smem_u32(smem);

    const int tid  = threadIdx.x;
    const int wid  = tid >> 5;
    const int lane = tid & 31;
    const int warp_m = wid & 1;
    const int warp_n = wid >> 1;
    const int lr = lane >> 2;
    const int lc = lane & 3;

    const int m0 = blockIdx.y * BM;
    const int n0 = blockIdx.x * BN;
    const int z = blockIdx.z;
    const __half* W = (z == 0) ? W0 : (z == 1) ? W1 : W2;
    void* C = (z == 0) ? C0 : (z == 1) ? C1 : C2;

    const uint32_t a_off = (uint32_t)(((warp_m * 64 + (lane & 15)) * LDH
                                       + (lane >> 4) * 8) * 2);
    const uint32_t b_off = (uint32_t)(((warp_n * 32 + (lane & 7)
                                        + ((lane >> 4) & 1) * 8) * LDH
                                       + ((lane >> 3) & 1) * 8) * 2);

    float acc[4][4][4];
#pragma unroll
    for (int mi = 0; mi < 4; mi++)
#pragma unroll
        for (int ni = 0; ni < 4; ni++)
#pragma unroll
            for (int k = 0; k < 4; k++) acc[mi][ni][k] = 0.0f;

#pragma unroll
    for (int s = 0; s < STAGES - 1; s++) {
        uint32_t sA = sbase + (uint32_t)(s * STAGE_HALVES) * 2;
        load_stage(A, W, m0, n0, s, sA, sA + 128 * LDH * 2, tid);
        cpa_commit();
    }

    for (int kt = 0; kt < NKT; kt++) {
        asm volatile("cp.async.wait_group %0;" :: "n"(STAGES - 2));
        __syncthreads();

        const int wt = kt + STAGES - 1;
        if (wt < NKT) {
            const int ws = wt % STAGES;
            uint32_t sA = sbase + (uint32_t)(ws * STAGE_HALVES) * 2;
            load_stage(A, W, m0, n0, wt, sA, sA + 128 * LDH * 2, tid);
        }
        cpa_commit();

        const int s = kt % STAGES;
        const uint32_t As_u = sbase + (uint32_t)(s * STAGE_HALVES) * 2;
        const uint32_t Bs_u = As_u + 128 * LDH * 2;

#pragma unroll
        for (int ks = 0; ks < 4; ks++) {
            uint32_t a[4][4], b[4][2];
#pragma unroll
            for (int mi = 0; mi < 4; mi++)
                ldsm4(a[mi][0], a[mi][1], a[mi][2], a[mi][3],
                      As_u + a_off + (uint32_t)((mi * 16 * LDH + ks * 16) * 2));
#pragma unroll
            for (int bp = 0; bp < 2; bp++)
                ldsm4(b[2 * bp][0], b[2 * bp][1], b[2 * bp + 1][0],
                      b[2 * bp + 1][1],
                      Bs_u + b_off + (uint32_t)((bp * 16 * LDH + ks * 16) * 2));
#pragma unroll
            for (int mi = 0; mi < 4; mi++)
#pragma unroll
                for (int ni = 0; ni < 4; ni++)
                    mma_f16(acc[mi][ni], a[mi], b[ni]);
        }
    }

    if (SPLIT) {
        __syncthreads();
        const int bb = m0 >> 11;
        const int t0 = m0 & (T_SEQ - 1);
        const int h0 = n0 >> 6;

        if (z < 2) {
#pragma unroll
            for (int mi = 0; mi < 4; mi++)
#pragma unroll
                for (int ni = 0; ni < 4; ni++)
#pragma unroll
                    for (int half_i = 0; half_i < 2; half_i++) {
                        const int ml = warp_m * 64 + mi * 16 + lr + half_i * 8;
                        const int nl = warp_n * 32 + ni * 8 + lc * 2;
                        *(__half2*)&smem[ml * LDO + nl] =
                            __floats2half2_rn(acc[mi][ni][half_i * 2],
                                              acc[mi][ni][half_i * 2 + 1]);
                    }
            __syncthreads();
            __half* Ch = (__half*)C;
#pragma unroll
            for (int p = 0; p < 8; p++) {
                int i = tid + p * 256;
                int c  = i & 7;
                int h2 = (i >> 3) & 1;
                int t  = i >> 4;
                uint4 val = *(uint4*)&smem[t * LDO + h2 * 64 + c * 8];
                __half* dst = Ch + (((size_t)(bb * NH + h0 + h2) * T_SEQ
                                     + t0 + t) * HD + c * 8);
                *(uint4*)dst = val;
            }
        } else {
#pragma unroll
            for (int mi = 0; mi < 4; mi++)
#pragma unroll
                for (int ni = 0; ni < 4; ni++)
#pragma unroll
                    for (int half_i = 0; half_i < 2; half_i++) {
                        const int ml = warp_m * 64 + mi * 16 + lr + half_i * 8;
                        const int nl = warp_n * 32 + ni * 8 + lc * 2;
                        smem[nl * LDO + ml] =
                            __float2half_rn(acc[mi][ni][half_i * 2]);
                        smem[(nl + 1) * LDO + ml] =
                            __float2half_rn(acc[mi][ni][half_i * 2 + 1]);
                    }
            __syncthreads();
            __half* Vt = (__half*)C;
#pragma unroll
            for (int p = 0; p < 8; p++) {
                int i = tid + p * 256;
                int c  = i & 15;
                int dn = i >> 4;
                int h2 = dn >> 6;
                int d  = dn & 63;
                uint4 val = *(uint4*)&smem[dn * LDO + c * 8];
                __half* dst = Vt + (((size_t)(bb * NH + h0 + h2) * HD + d)
                                    * T_SEQ + t0 + c * 8);
                *(uint4*)dst = val;
            }
        }
    } else {
#pragma unroll
        for (int mi = 0; mi < 4; mi++) {
#pragma unroll
            for (int ni = 0; ni < 4; ni++) {
                const int n = n0 + warp_n * 32 + ni * 8 + lc * 2;
#pragma unroll
                for (int half_i = 0; half_i < 2; half_i++) {
                    const int mg = m0 + warp_m * 64 + mi * 16 + lr + half_i * 8;
                    float v0 = acc[mi][ni][half_i * 2 + 0];
                    float v1 = acc[mi][ni][half_i * 2 + 1];
                    if (BIAS) { v0 += bias[n]; v1 += bias[n + 1]; }
                    float* dst = (float*)C + (size_t)mg * DMODEL + n;
                    *(float2*)dst = make_float2(v0, v1);
                }
            }
        }
    }
}

// ---------------------------------------------------------------------------
// Tensor-core flash attention (causal), fp16; S uses fp16 ACCUMULATORS
// ---------------------------------------------------------------------------
__device__ __forceinline__ void fa_load_kv(const __half* __restrict__ Kh,
                                           const __half* __restrict__ Vtg,
                                           uint32_t ks, uint32_t vs,
                                           size_t hb, size_t vb, int j0, int tid)
{
#pragma unroll
    for (int p = 0; p < 4; p++) {
        int i = p * 128 + tid;
        int r = i >> 3, c = i & 7;
        cpa16(ks + (uint32_t)(r * 144 + c * 16),
              Kh + hb + (size_t)(j0 + r) * HD + c * 8);
    }
#pragma unroll
    for (int p = 0; p < 4; p++) {
        int i = p * 128 + tid;
        int d = i >> 3, c = i & 7;
        cpa16(vs + (uint32_t)(d * 144 + c * 16),
              Vtg + vb + (size_t)d * T_SEQ + j0 + c * 8);
    }
}

__global__ void __launch_bounds__(128, 4)
flash_attn_tc(const __half* __restrict__ Qh, const __half* __restrict__ Kh,
              const __half* __restrict__ Vtg, __half* __restrict__ ctx)
{
    extern __shared__ __align__(16) char sm[];

    const int qt = (T_SEQ / 64 - 1) - blockIdx.x;   // heavy first
    const int h  = blockIdx.y;
    const int b  = blockIdx.z;
    const int i0 = qt * 64;
    const size_t hb = ((size_t)(b * NH + h)) * T_SEQ * HD;
    const size_t vb = ((size_t)(b * NH + h)) * HD * T_SEQ;

    const int tid  = threadIdx.x;
    const int wid  = tid >> 5;
    const int lane = tid & 31;
    const int lr = lane >> 2;
    const int lc = lane & 3;

    const uint32_t Qs_u  = smem_u32(sm) + FA_QS;
    const uint32_t Ks_u0 = smem_u32(sm) + FA_KS0;
    const uint32_t Vs_u0 = smem_u32(sm) + FA_VS0;

    const uint32_t qa_off = (uint32_t)(((wid * 16 + (lane & 15)) * 72
                                        + (lane >> 4) * 8) * 2);
    const uint32_t kb_off = (uint32_t)((((lane & 7) + ((lane >> 4) & 1) * 8) * 72
                                        + ((lane >> 3) & 1) * 8) * 2);

    {
#pragma unroll
        for (int p = 0; p < 4; p++) {
            int i = p * 128 + tid;
            int r = i >> 3, c = i & 7;
            cpa16(Qs_u + (uint32_t)(r * 144 + c * 16),
                  Qh + hb + (size_t)(i0 + r) * HD + c * 8);
        }
        fa_load_kv(Kh, Vtg, Ks_u0, Vs_u0, hb, vb, 0, tid);
        cpa_commit();
    }

    float m0 = -1e30f, m1 = -1e30f, l0 = 0.0f, l1 = 0.0f;
    float o[8][4];
#pragma unroll
    for (int nf = 0; nf < 8; nf++)
#pragma unroll
        for (int j = 0; j < 4; j++) o[nf][j] = 0.0f;

    const int qr = wid * 16 + lr;
    const float kk = 0.18033688011112042f;  // log2(e)/sqrt(64)

    for (int jt = 0; jt <= qt; jt++) {
        if (jt < qt) {
            const int nb = (jt + 1) & 1;
            fa_load_kv(Kh, Vtg, Ks_u0 + nb * 9216, Vs_u0 + nb * 9216,
                       hb, vb, (jt + 1) * 64, tid);
        }
        cpa_commit();
        asm volatile("cp.async.wait_group 1;");
        __syncthreads();

        const uint32_t Ks_u = Ks_u0 + (jt & 1) * 9216;
        const uint32_t Vs_u = Vs_u0 + (jt & 1) * 9216;

        // ---- S = Q @ K^T (fp16 acc) ----
        uint32_t sh[8][2];
#pragma unroll
        for (int nf = 0; nf < 8; nf++) { sh[nf][0] = 0u; sh[nf][1] = 0u; }

#pragma unroll
        for (int kc = 0; kc < 4; kc++) {
            uint32_t a[4];
            ldsm4(a[0], a[1], a[2], a[3], Qs_u + qa_off + kc * 32);
#pragma unroll
            for (int np = 0; np < 4; np++) {
                uint32_t b0, b1, b2, b3;
                ldsm4(b0, b1, b2, b3,
                      Ks_u + kb_off + (uint32_t)((np * 16 * 72 + kc * 16) * 2));
                uint32_t bl[2] = { b0, b1 };
                uint32_t bh[2] = { b2, b3 };
                mma_f16acc(sh[2 * np],     a, bl);
                mma_f16acc(sh[2 * np + 1], a, bh);
            }
        }

        float s[8][4];
#pragma unroll
        for (int nf = 0; nf < 8; nf++) {
            float2 lo = __half22float2(*(__half2*)&sh[nf][0]);
            float2 hi = __half22float2(*(__half2*)&sh[nf][1]);
            s[nf][0] = lo.x; s[nf][1] = lo.y;
            s[nf][2] = hi.x; s[nf][3] = hi.y;
        }

        // ---- online softmax (exp2 domain) ----
        const bool diag = (jt == qt);
        float mx0 = -1e30f, mx1 = -1e30f;
#pragma unroll
        for (int nf = 0; nf < 8; nf++) {
            float e0 = s[nf][0] * kk, e1 = s[nf][1] * kk;
            float e2 = s[nf][2] * kk, e3 = s[nf][3] * kk;
            if (diag) {
                const int c0 = nf * 8 + lc * 2, c1 = c0 + 1;
                if (c0 > qr)     e0 = -1e30f;
                if (c1 > qr)     e1 = -1e30f;
                if (c0 > qr + 8) e2 = -1e30f;
                if (c1 > qr + 8) e3 = -1e30f;
            }
            s[nf][0] = e0; s[nf][1] = e1; s[nf][2] = e2; s[nf][3] = e3;
            mx0 = fmaxf(mx0, fmaxf(e0, e1));
            mx1 = fmaxf(mx1, fmaxf(e2, e3));
        }
        mx0 = fmaxf(mx0, __shfl_xor_sync(0xffffffffu, mx0, 1));
        mx0 = fmaxf(mx0, __shfl_xor_sync(0xffffffffu, mx0, 2));
        mx1 = fmaxf(mx1, __shfl_xor_sync(0xffffffffu, mx1, 1));
        mx1 = fmaxf(mx1, __shfl_xor_sync(0xffffffffu, mx1, 2));

        const float mn0 = fmaxf(m0, mx0), mn1 = fmaxf(m1, mx1);
        const float al0 = ex2(m0 - mn0),  al1 = ex2(m1 - mn1);

        uint32_t ph[8][2];
        float sum0 = 0.0f, sum1 = 0.0f;
#pragma unroll
        for (int nf = 0; nf < 8; nf++) {
            float p0 = ex2(s[nf][0] - mn0), p1 = ex2(s[nf][1] - mn0);
            float p2 = ex2(s[nf][2] - mn1), p3 = ex2(s[nf][3] - mn1);
            sum0 += p0 + p1;
            sum1 += p2 + p3;
            __half2 hlo = __floats2half2_rn(p0, p1);
            __half2 hhi = __floats2half2_rn(p2, p3);
            ph[nf][0] = *(uint32_t*)&hlo;
            ph[nf][1] = *(uint32_t*)&hhi;
        }
        sum0 += __shfl_xor_sync(0xffffffffu, sum0, 1);
        sum0 += __shfl_xor_sync(0xffffffffu, sum0, 2);
        sum1 += __shfl_xor_sync(0xffffffffu, sum1, 1);
        sum1 += __shfl_xor_sync(0xffffffffu, sum1, 2);
        l0 = l0 * al0 + sum0;
        l1 = l1 * al1 + sum1;
        m0 = mn0; m1 = mn1;
#pragma unroll
        for (int nf = 0; nf < 8; nf++) {
            o[nf][0] *= al0; o[nf][1] *= al0;
            o[nf][2] *= al1; o[nf][3] *= al1;
        }

        // ---- O += P @ V (fp32 acc) ----
#pragma unroll
        for (int kc = 0; kc < 4; kc++) {
            uint32_t a[4] = { ph[2 * kc][0], ph[2 * kc][1],
                              ph[2 * kc + 1][0], ph[2 * kc + 1][1] };
#pragma unroll
            for (int np = 0; np < 4; np++) {
                uint32_t b0, b1, b2, b3;
                ldsm4(b0, b1, b2, b3,
                      Vs_u + kb_off + (uint32_t)((np * 16 * 72 + kc * 16) * 2));
                uint32_t bl[2] = { b0, b1 };
                uint32_t bh[2] = { b2, b3 };
                mma_f16(o[2 * np],     a, bl);
                mma_f16(o[2 * np + 1], a, bh);
            }
        }
        __syncthreads();
    }

    // ---- epilogue ----
    const float inv0 = 1.0f / l0, inv1 = 1.0f / l1;
    const int t_lo = i0 + qr;
#pragma unroll
    for (int nf = 0; nf < 8; nf++) {
        const int d = nf * 8 + lc * 2;
        __half* p0 = ctx + ((size_t)(b * T_SEQ + t_lo)) * DMODEL + h * HD + d;
        *(__half2*)p0 = __floats2half2_rn(o[nf][0] * inv0, o[nf][1] * inv0);
        __half* p1 = p0 + (size_t)8 * DMODEL;
        *(__half2*)p1 = __floats2half2_rn(o[nf][2] * inv1, o[nf][3] * inv1);
    }
}

// ---------------------------------------------------------------------------

extern "C" void kernel_launch(void* const* d_in, const int* in_sizes, int n_in,
                              void* d_out, int out_size)
{
    const float* x  = (const float*)d_in[0];
    const float* wq = (const float*)d_in[1];
    const float* wk = (const float*)d_in[2];
    const float* wv = (const float*)d_in[3];
    const float* wo = (const float*)d_in[4];
    const float* bo = (const float*)d_in[5];
    float* out = (float*)d_out;

    __half *pXh, *pWh, *pQh, *pKh, *pVt, *pCtx;
    cudaGetSymbolAddress((void**)&pXh, g_xh);
    cudaGetSymbolAddress((void**)&pWh, g_wh);
    cudaGetSymbolAddress((void**)&pQh, g_Qh);
    cudaGetSymbolAddress((void**)&pKh, g_Kh);
    cudaGetSymbolAddress((void**)&pVt, g_Vt);
    cudaGetSymbolAddress((void**)&pCtx, g_ctxh);

    __half* pWq = pWh;
    __half* pWk = pWh + (size_t)DMODEL * DMODEL;
    __half* pWv = pWh + 2 * (size_t)DMODEL * DMODEL;
    __half* pWo = pWh + 3 * (size_t)DMODEL * DMODEL;

    cudaFuncSetAttribute(gemm_fp16<true, false>,
                         cudaFuncAttributeMaxDynamicSharedMemorySize, GEMM_SMEM);
    cudaFuncSetAttribute(gemm_fp16<false, true>,
                         cudaFuncAttributeMaxDynamicSharedMemorySize, GEMM_SMEM);
    cudaFuncSetAttribute(flash_attn_tc,
                         cudaFuncAttributeMaxDynamicSharedMemorySize, FA_SMEM);

    // 1) single-launch f32->fp16 conversion (x + 4 weights)
    {
        int total = XN4 + 4 * WN4;
        cvt_all<<<total / 256, 256>>>(
            (const float4*)x, (const float4*)wq, (const float4*)wk,
            (const float4*)wv, (const float4*)wo, (uint2*)pXh, (uint2*)pWh);
    }

    // 2) fused QKV projections (fp16 MMA, f32 acc)
    {
        dim3 grid(DMODEL / BN, M_ROWS / BM, 3);
        gemm_fp16<true, false><<<grid, 256, GEMM_SMEM>>>(
            pXh, pWq, pWk, pWv, pQh, pKh, pVt, nullptr);
    }

    // 3) tensor-core flash attention (fp16; S fp16-acc)
    {
        dim3 fgrid(T_SEQ / 64, NH, BATCH_N);
        flash_attn_tc<<<fgrid, 128, FA_SMEM>>>(pQh, pKh, pVt, pCtx);
    }

    // 4) output projection + bias (fp32 out)
    {
        dim3 grid(DMODEL / BN, M_ROWS / BM, 1);
        gemm_fp16<false, true><<<grid, 256, GEMM_SMEM>>>(
            pCtx, pWo, pWo, pWo, out, out, out, bo);
    }
}